// round 4
// baseline (speedup 1.0000x reference)
#include <cuda_runtime.h>

#define NN 100000
#define EE 1600000

// Static device scratch (allocation-free per harness rules)
__device__ float g_rs[NN];    // ns[n] * r_k[n]  (value gathered in scatter pass)
__device__ float g_acc[NN];   // edge-scatter accumulator
__device__ float g_ns[NN];    // out_deg^-1/2 (src norm); holds raw out-degree first
__device__ float g_nd[NN];    // in_deg^-1/2  (dst norm); holds raw in-degree first
__device__ int   g_src[EE];   // int32 decoded edge indices
__device__ int   g_dst[EE];
__device__ float g_scal[8];   // s0..s5, w
__device__ int   g_is64;      // 1 if edge indices are int64, 0 if int32

// ---------------------------------------------------------------------------
// Probe index dtype (warp-parallel). Reads first 256 elements as int64 (2 KB —
// safe for both int32 (6.4MB) and int64 (12.8MB) buffers). True int64 indices
// are all in [0, NN); aliased int32 pairs exceed NN with probability ~1.
// ---------------------------------------------------------------------------
__global__ void k_probe(const unsigned long long* __restrict__ src) {
    int t = threadIdx.x;                       // 256 threads
    int bad = (src[t] >= (unsigned long long)NN) ? 1 : 0;
    __shared__ int s_bad;
    if (t == 0) s_bad = 0;
    __syncthreads();
    if (__syncthreads_or(bad)) { if (t == 0) s_bad = 1; }
    __syncthreads();
    if (t == 0) g_is64 = s_bad ? 0 : 1;
}

// ---------------------------------------------------------------------------
// Collapse the linear channel path: suffix vectors u_l = W_l @ u_{l+1},
// w = W0@...@W5 (scalar), s_l = b_l . u_{l+1}.
// ---------------------------------------------------------------------------
__global__ void k_scalars(const float* __restrict__ W0, const float* __restrict__ b0,
                          const float* __restrict__ W1, const float* __restrict__ b1,
                          const float* __restrict__ W2, const float* __restrict__ b2,
                          const float* __restrict__ W3, const float* __restrict__ b3,
                          const float* __restrict__ W4, const float* __restrict__ b4,
                          const float* __restrict__ W5, const float* __restrict__ b5) {
    __shared__ float u5[32], u4[64], u3[128], u2[64], u1[32];
    int t = threadIdx.x;

    if (t < 32) u5[t] = W5[t];                       // W5: 32x1
    __syncthreads();
    if (t < 64) {                                    // W4: 64x32
        float s = 0.f;
        for (int j = 0; j < 32; j++) s += W4[t * 32 + j] * u5[j];
        u4[t] = s;
    }
    __syncthreads();
    if (t < 128) {                                   // W3: 128x64
        float s = 0.f;
        for (int j = 0; j < 64; j++) s += W3[t * 64 + j] * u4[j];
        u3[t] = s;
    }
    __syncthreads();
    if (t < 64) {                                    // W2: 64x128
        float s = 0.f;
        for (int j = 0; j < 128; j++) s += W2[t * 128 + j] * u3[j];
        u2[t] = s;
    }
    __syncthreads();
    if (t < 32) {                                    // W1: 32x64
        float s = 0.f;
        for (int j = 0; j < 64; j++) s += W1[t * 64 + j] * u2[j];
        u1[t] = s;
    }
    __syncthreads();
    if (t == 0) {
        float w = 0.f, s0 = 0.f;
        for (int j = 0; j < 32; j++)  { w += W0[j] * u1[j]; s0 += b0[j] * u1[j]; }
        float s1 = 0.f; for (int j = 0; j < 64;  j++) s1 += b1[j] * u2[j];
        float s2 = 0.f; for (int j = 0; j < 128; j++) s2 += b2[j] * u3[j];
        float s3 = 0.f; for (int j = 0; j < 64;  j++) s3 += b3[j] * u4[j];
        float s4 = 0.f; for (int j = 0; j < 32;  j++) s4 += b4[j] * u5[j];
        g_scal[0] = s0; g_scal[1] = s1; g_scal[2] = s2;
        g_scal[3] = s3; g_scal[4] = s4; g_scal[5] = b5[0];
        g_scal[6] = w;
    }
}

// Zero degree + accumulator arrays (float4; NN % 4 == 0).
__global__ void k_zero() {
    int n = blockIdx.x * blockDim.x + threadIdx.x;
    if (n < NN / 4) {
        float4 z = make_float4(0.f, 0.f, 0.f, 0.f);
        reinterpret_cast<float4*>(g_ns)[n]  = z;
        reinterpret_cast<float4*>(g_nd)[n]  = z;
        reinterpret_cast<float4*>(g_acc)[n] = z;
    }
}

// Decode 4 edges/thread (int32 or int64 per probe flag), clamp, store int4,
// accumulate degrees (float atomics are exact for counts < 2^24).
__global__ void k_edges(const void* __restrict__ srcv,
                        const void* __restrict__ dstv) {
    int i = blockIdx.x * blockDim.x + threadIdx.x;
    int base = i * 4;
    if (base >= EE) return;

    long long sl[4], dl[4];
    if (g_is64) {
        longlong2 sa = reinterpret_cast<const longlong2*>(srcv)[i * 2];
        longlong2 sb = reinterpret_cast<const longlong2*>(srcv)[i * 2 + 1];
        longlong2 da = reinterpret_cast<const longlong2*>(dstv)[i * 2];
        longlong2 db = reinterpret_cast<const longlong2*>(dstv)[i * 2 + 1];
        sl[0] = sa.x; sl[1] = sa.y; sl[2] = sb.x; sl[3] = sb.y;
        dl[0] = da.x; dl[1] = da.y; dl[2] = db.x; dl[3] = db.y;
    } else {
        int4 sa = reinterpret_cast<const int4*>(srcv)[i];
        int4 da = reinterpret_cast<const int4*>(dstv)[i];
        sl[0] = sa.x; sl[1] = sa.y; sl[2] = sa.z; sl[3] = sa.w;
        dl[0] = da.x; dl[1] = da.y; dl[2] = da.z; dl[3] = da.w;
    }

    int s[4], d[4];
#pragma unroll
    for (int j = 0; j < 4; j++) {
        s[j] = (sl[j] < 0) ? 0 : (sl[j] >= NN ? NN - 1 : (int)sl[j]);
        d[j] = (dl[j] < 0) ? 0 : (dl[j] >= NN ? NN - 1 : (int)dl[j]);
    }
    reinterpret_cast<int4*>(g_src)[i] = make_int4(s[0], s[1], s[2], s[3]);
    reinterpret_cast<int4*>(g_dst)[i] = make_int4(d[0], d[1], d[2], d[3]);
#pragma unroll
    for (int j = 0; j < 4; j++) atomicAdd(&g_ns[s[j]], 1.f);
#pragma unroll
    for (int j = 0; j < 4; j++) atomicAdd(&g_nd[d[j]], 1.f);
}

// Finalize norms; r0 = w * x; stage rs = ns * r0. (float4; NN % 4 == 0)
__global__ void k_init(const float* __restrict__ x) {
    int n = blockIdx.x * blockDim.x + threadIdx.x;
    if (n < NN / 4) {
        float w = g_scal[6];
        float4 dg_s = reinterpret_cast<float4*>(g_ns)[n];
        float4 dg_d = reinterpret_cast<float4*>(g_nd)[n];
        float4 xv   = reinterpret_cast<const float4*>(x)[n];
        float4 ns, nd, rs;
        ns.x = rsqrtf(fmaxf(dg_s.x, 1.f)); nd.x = rsqrtf(fmaxf(dg_d.x, 1.f));
        ns.y = rsqrtf(fmaxf(dg_s.y, 1.f)); nd.y = rsqrtf(fmaxf(dg_d.y, 1.f));
        ns.z = rsqrtf(fmaxf(dg_s.z, 1.f)); nd.z = rsqrtf(fmaxf(dg_d.z, 1.f));
        ns.w = rsqrtf(fmaxf(dg_s.w, 1.f)); nd.w = rsqrtf(fmaxf(dg_d.w, 1.f));
        rs.x = ns.x * w * xv.x; rs.y = ns.y * w * xv.y;
        rs.z = ns.z * w * xv.z; rs.w = ns.w * w * xv.w;
        reinterpret_cast<float4*>(g_ns)[n] = ns;
        reinterpret_cast<float4*>(g_nd)[n] = nd;
        reinterpret_cast<float4*>(g_rs)[n] = rs;
    }
}

// One propagation hop: acc[dst] += rs[src]. 8 edges/thread (EE % 8 == 0)
// — 8 independent gathers in flight before the REDs for MLP.
__global__ void k_scatter() {
    int i = blockIdx.x * blockDim.x + threadIdx.x;
    if (i >= EE / 8) return;
    int4 s0 = reinterpret_cast<const int4*>(g_src)[i * 2];
    int4 s1 = reinterpret_cast<const int4*>(g_src)[i * 2 + 1];
    int4 d0 = reinterpret_cast<const int4*>(g_dst)[i * 2];
    int4 d1 = reinterpret_cast<const int4*>(g_dst)[i * 2 + 1];
    float v0 = __ldg(&g_rs[s0.x]);
    float v1 = __ldg(&g_rs[s0.y]);
    float v2 = __ldg(&g_rs[s0.z]);
    float v3 = __ldg(&g_rs[s0.w]);
    float v4 = __ldg(&g_rs[s1.x]);
    float v5 = __ldg(&g_rs[s1.y]);
    float v6 = __ldg(&g_rs[s1.z]);
    float v7 = __ldg(&g_rs[s1.w]);
    atomicAdd(&g_acc[d0.x], v0);
    atomicAdd(&g_acc[d0.y], v1);
    atomicAdd(&g_acc[d0.z], v2);
    atomicAdd(&g_acc[d0.w], v3);
    atomicAdd(&g_acc[d1.x], v4);
    atomicAdd(&g_acc[d1.y], v5);
    atomicAdd(&g_acc[d1.z], v6);
    atomicAdd(&g_acc[d1.w], v7);
}

// r_{k+1} = nd*acc + s_k; stage rs = ns*r_{k+1}; re-zero acc. (float4)
__global__ void k_post(int k) {
    int n = blockIdx.x * blockDim.x + threadIdx.x;
    if (n < NN / 4) {
        float sk = g_scal[k];
        float4 nd = reinterpret_cast<float4*>(g_nd)[n];
        float4 ac = reinterpret_cast<float4*>(g_acc)[n];
        float4 ns = reinterpret_cast<float4*>(g_ns)[n];
        float4 rs;
        rs.x = ns.x * (nd.x * ac.x + sk);
        rs.y = ns.y * (nd.y * ac.y + sk);
        rs.z = ns.z * (nd.z * ac.z + sk);
        rs.w = ns.w * (nd.w * ac.w + sk);
        reinterpret_cast<float4*>(g_rs)[n] = rs;
        reinterpret_cast<float4*>(g_acc)[n] = make_float4(0.f, 0.f, 0.f, 0.f);
    }
}

// Final hop epilogue: out = |nd*acc + s5| (float4)
__global__ void k_final(float* __restrict__ out) {
    int n = blockIdx.x * blockDim.x + threadIdx.x;
    if (n < NN / 4) {
        float s5 = g_scal[5];
        float4 nd = reinterpret_cast<float4*>(g_nd)[n];
        float4 ac = reinterpret_cast<float4*>(g_acc)[n];
        float4 o;
        o.x = fabsf(nd.x * ac.x + s5);
        o.y = fabsf(nd.y * ac.y + s5);
        o.z = fabsf(nd.z * ac.z + s5);
        o.w = fabsf(nd.w * ac.w + s5);
        reinterpret_cast<float4*>(out)[n] = o;
    }
}

extern "C" void kernel_launch(void* const* d_in, const int* in_sizes, int n_in,
                              void* d_out, int out_size) {
    // Layout A (dict order): x, src, dst, W0,b0..W5,b5
    // Layout B (sorted):     W0..W5, b0..b5, dst, src, x
    const float *x, *W0, *b0, *W1, *b1, *W2, *b2, *W3, *b3, *W4, *b4, *W5, *b5;
    const void *src, *dst;

    if (in_sizes[0] == NN) {
        x   = (const float*)d_in[0];
        src = d_in[1];
        dst = d_in[2];
        W0 = (const float*)d_in[3];  b0 = (const float*)d_in[4];
        W1 = (const float*)d_in[5];  b1 = (const float*)d_in[6];
        W2 = (const float*)d_in[7];  b2 = (const float*)d_in[8];
        W3 = (const float*)d_in[9];  b3 = (const float*)d_in[10];
        W4 = (const float*)d_in[11]; b4 = (const float*)d_in[12];
        W5 = (const float*)d_in[13]; b5 = (const float*)d_in[14];
    } else {
        W0 = (const float*)d_in[0];  W1 = (const float*)d_in[1];
        W2 = (const float*)d_in[2];  W3 = (const float*)d_in[3];
        W4 = (const float*)d_in[4];  W5 = (const float*)d_in[5];
        b0 = (const float*)d_in[6];  b1 = (const float*)d_in[7];
        b2 = (const float*)d_in[8];  b3 = (const float*)d_in[9];
        b4 = (const float*)d_in[10]; b5 = (const float*)d_in[11];
        dst = d_in[12];
        src = d_in[13];
        x   = (const float*)d_in[14];
    }
    float* out = (float*)d_out;

    const int TB = 256;
    const int GN4 = (NN / 4 + TB - 1) / TB;      // node kernels, float4
    const int GE4 = (EE / 4 + TB - 1) / TB;      // edge decode, 4/thread
    const int GS8 = (EE / 8 + TB - 1) / TB;      // scatter, 8/thread

    k_probe<<<1, 256>>>((const unsigned long long*)src);
    k_scalars<<<1, 128>>>(W0, b0, W1, b1, W2, b2, W3, b3, W4, b4, W5, b5);
    k_zero<<<GN4, TB>>>();
    k_edges<<<GE4, TB>>>(src, dst);
    k_init<<<GN4, TB>>>(x);

    for (int k = 0; k < 5; k++) {
        k_scatter<<<GS8, TB>>>();
        k_post<<<GN4, TB>>>(k);
    }
    k_scatter<<<GS8, TB>>>();
    k_final<<<GN4, TB>>>(out);
}

// round 5
// speedup vs baseline: 1.0277x; 1.0277x over previous
#include <cuda_runtime.h>

#define NN 100000
#define EE 1600000

// Static device scratch (allocation-free per harness rules)
__device__ float g_rs[NN];     // ns[n] * r_k[n]  (value gathered in scatter pass)
__device__ float g_acc[NN];    // edge-scatter accumulator
__device__ float g_ns[NN];     // out_deg^-1/2; holds raw out-degree first
__device__ float g_nd[NN];     // in_deg^-1/2;  holds raw in-degree first
__device__ int2  g_edge[EE];   // packed (src, dst) int32 pairs
__device__ float g_scal[8];    // s0..s5, w
__device__ int   g_is64;       // 1 if edge indices are int64, 0 if int32

// ---------------------------------------------------------------------------
// Fused setup kernel. Block 0: collapse the linear channel path into scalars
// (suffix vectors u_l = W_l@u_{l+1}; w = W0..W5; s_l = b_l.u_{l+1}).
// Block 1: probe index dtype (reads first 256 elems as u64 — 2 KB, safe for
// both int32 (6.4MB) and int64 (12.8MB) buffers; true int64 indices are all
// < NN, aliased int32 pairs exceed NN with probability ~1).
// Blocks 2..: zero degree + accumulator arrays (float4).
// ---------------------------------------------------------------------------
__global__ void k_setup(const unsigned long long* __restrict__ srcp,
                        const float* __restrict__ W0, const float* __restrict__ b0,
                        const float* __restrict__ W1, const float* __restrict__ b1,
                        const float* __restrict__ W2, const float* __restrict__ b2,
                        const float* __restrict__ W3, const float* __restrict__ b3,
                        const float* __restrict__ W4, const float* __restrict__ b4,
                        const float* __restrict__ W5, const float* __restrict__ b5) {
    int t = threadIdx.x;
    if (blockIdx.x == 0) {
        __shared__ float u5[32], u4[64], u3[128], u2[64], u1[32];
        if (t < 32) u5[t] = W5[t];                       // W5: 32x1
        __syncthreads();
        if (t < 64) {                                    // W4: 64x32
            float s = 0.f;
            for (int j = 0; j < 32; j++) s += W4[t * 32 + j] * u5[j];
            u4[t] = s;
        }
        __syncthreads();
        if (t < 128) {                                   // W3: 128x64
            float s = 0.f;
            for (int j = 0; j < 64; j++) s += W3[t * 64 + j] * u4[j];
            u3[t] = s;
        }
        __syncthreads();
        if (t < 64) {                                    // W2: 64x128
            float s = 0.f;
            for (int j = 0; j < 128; j++) s += W2[t * 128 + j] * u3[j];
            u2[t] = s;
        }
        __syncthreads();
        if (t < 32) {                                    // W1: 32x64
            float s = 0.f;
            for (int j = 0; j < 64; j++) s += W1[t * 64 + j] * u2[j];
            u1[t] = s;
        }
        __syncthreads();
        if (t == 0) {
            float w = 0.f, s0 = 0.f;
            for (int j = 0; j < 32; j++)  { w += W0[j] * u1[j]; s0 += b0[j] * u1[j]; }
            float s1 = 0.f; for (int j = 0; j < 64;  j++) s1 += b1[j] * u2[j];
            float s2 = 0.f; for (int j = 0; j < 128; j++) s2 += b2[j] * u3[j];
            float s3 = 0.f; for (int j = 0; j < 64;  j++) s3 += b3[j] * u4[j];
            float s4 = 0.f; for (int j = 0; j < 32;  j++) s4 += b4[j] * u5[j];
            g_scal[0] = s0; g_scal[1] = s1; g_scal[2] = s2;
            g_scal[3] = s3; g_scal[4] = s4; g_scal[5] = b5[0];
            g_scal[6] = w;
        }
    } else if (blockIdx.x == 1) {
        int bad = (srcp[t] >= (unsigned long long)NN) ? 1 : 0;
        int any = __syncthreads_or(bad);
        if (t == 0) g_is64 = any ? 0 : 1;
    } else {
        int n = (blockIdx.x - 2) * blockDim.x + t;
        if (n < NN / 4) {
            float4 z = make_float4(0.f, 0.f, 0.f, 0.f);
            reinterpret_cast<float4*>(g_ns)[n]  = z;
            reinterpret_cast<float4*>(g_nd)[n]  = z;
            reinterpret_cast<float4*>(g_acc)[n] = z;
        }
    }
}

// Decode 1 edge/thread (int32 or int64 per probe flag), clamp, store packed
// int2, accumulate degrees (float atomics exact for counts < 2^24).
__global__ void k_edges(const void* __restrict__ srcv,
                        const void* __restrict__ dstv) {
    int e = blockIdx.x * blockDim.x + threadIdx.x;
    if (e < EE) {
        long long sl, dl;
        if (g_is64) {
            sl = ((const long long*)srcv)[e];
            dl = ((const long long*)dstv)[e];
        } else {
            sl = ((const int*)srcv)[e];
            dl = ((const int*)dstv)[e];
        }
        int s = (sl < 0) ? 0 : (sl >= NN ? NN - 1 : (int)sl);
        int d = (dl < 0) ? 0 : (dl >= NN ? NN - 1 : (int)dl);
        g_edge[e] = make_int2(s, d);
        atomicAdd(&g_ns[s], 1.f);
        atomicAdd(&g_nd[d], 1.f);
    }
}

// Finalize norms; r0 = w * x; stage rs = ns * r0. (float4; NN % 4 == 0)
__global__ void k_init(const float* __restrict__ x) {
    int n = blockIdx.x * blockDim.x + threadIdx.x;
    if (n < NN / 4) {
        float w = g_scal[6];
        float4 dg_s = reinterpret_cast<float4*>(g_ns)[n];
        float4 dg_d = reinterpret_cast<float4*>(g_nd)[n];
        float4 xv   = reinterpret_cast<const float4*>(x)[n];
        float4 ns, nd, rs;
        ns.x = rsqrtf(fmaxf(dg_s.x, 1.f)); nd.x = rsqrtf(fmaxf(dg_d.x, 1.f));
        ns.y = rsqrtf(fmaxf(dg_s.y, 1.f)); nd.y = rsqrtf(fmaxf(dg_d.y, 1.f));
        ns.z = rsqrtf(fmaxf(dg_s.z, 1.f)); nd.z = rsqrtf(fmaxf(dg_d.z, 1.f));
        ns.w = rsqrtf(fmaxf(dg_s.w, 1.f)); nd.w = rsqrtf(fmaxf(dg_d.w, 1.f));
        rs.x = ns.x * w * xv.x; rs.y = ns.y * w * xv.y;
        rs.z = ns.z * w * xv.z; rs.w = ns.w * w * xv.w;
        reinterpret_cast<float4*>(g_ns)[n] = ns;
        reinterpret_cast<float4*>(g_nd)[n] = nd;
        reinterpret_cast<float4*>(g_rs)[n] = rs;
    }
}

// One propagation hop: acc[dst] += rs[src]. 2 edges/thread via one int4 load
// (2.5 memory instructions per edge; 800k threads keep latency hidden).
__global__ void k_scatter() {
    int i = blockIdx.x * blockDim.x + threadIdx.x;
    if (i < EE / 2) {
        int4 p = reinterpret_cast<const int4*>(g_edge)[i];   // (s0,d0,s1,d1)
        float v0 = __ldg(&g_rs[p.x]);
        float v1 = __ldg(&g_rs[p.z]);
        atomicAdd(&g_acc[p.y], v0);
        atomicAdd(&g_acc[p.w], v1);
    }
}

// r_{k+1} = nd*acc + s_k; stage rs = ns*r_{k+1}; re-zero acc. (float4)
__global__ void k_post(int k) {
    int n = blockIdx.x * blockDim.x + threadIdx.x;
    if (n < NN / 4) {
        float sk = g_scal[k];
        float4 nd = reinterpret_cast<float4*>(g_nd)[n];
        float4 ac = reinterpret_cast<float4*>(g_acc)[n];
        float4 ns = reinterpret_cast<float4*>(g_ns)[n];
        float4 rs;
        rs.x = ns.x * (nd.x * ac.x + sk);
        rs.y = ns.y * (nd.y * ac.y + sk);
        rs.z = ns.z * (nd.z * ac.z + sk);
        rs.w = ns.w * (nd.w * ac.w + sk);
        reinterpret_cast<float4*>(g_rs)[n] = rs;
        reinterpret_cast<float4*>(g_acc)[n] = make_float4(0.f, 0.f, 0.f, 0.f);
    }
}

// Final hop epilogue: out = |nd*acc + s5| (float4)
__global__ void k_final(float* __restrict__ out) {
    int n = blockIdx.x * blockDim.x + threadIdx.x;
    if (n < NN / 4) {
        float s5 = g_scal[5];
        float4 nd = reinterpret_cast<float4*>(g_nd)[n];
        float4 ac = reinterpret_cast<float4*>(g_acc)[n];
        float4 o;
        o.x = fabsf(nd.x * ac.x + s5);
        o.y = fabsf(nd.y * ac.y + s5);
        o.z = fabsf(nd.z * ac.z + s5);
        o.w = fabsf(nd.w * ac.w + s5);
        reinterpret_cast<float4*>(out)[n] = o;
    }
}

extern "C" void kernel_launch(void* const* d_in, const int* in_sizes, int n_in,
                              void* d_out, int out_size) {
    // Layout A (dict order): x, src, dst, W0,b0..W5,b5
    // Layout B (sorted):     W0..W5, b0..b5, dst, src, x
    const float *x, *W0, *b0, *W1, *b1, *W2, *b2, *W3, *b3, *W4, *b4, *W5, *b5;
    const void *src, *dst;

    if (in_sizes[0] == NN) {
        x   = (const float*)d_in[0];
        src = d_in[1];
        dst = d_in[2];
        W0 = (const float*)d_in[3];  b0 = (const float*)d_in[4];
        W1 = (const float*)d_in[5];  b1 = (const float*)d_in[6];
        W2 = (const float*)d_in[7];  b2 = (const float*)d_in[8];
        W3 = (const float*)d_in[9];  b3 = (const float*)d_in[10];
        W4 = (const float*)d_in[11]; b4 = (const float*)d_in[12];
        W5 = (const float*)d_in[13]; b5 = (const float*)d_in[14];
    } else {
        W0 = (const float*)d_in[0];  W1 = (const float*)d_in[1];
        W2 = (const float*)d_in[2];  W3 = (const float*)d_in[3];
        W4 = (const float*)d_in[4];  W5 = (const float*)d_in[5];
        b0 = (const float*)d_in[6];  b1 = (const float*)d_in[7];
        b2 = (const float*)d_in[8];  b3 = (const float*)d_in[9];
        b4 = (const float*)d_in[10]; b5 = (const float*)d_in[11];
        dst = d_in[12];
        src = d_in[13];
        x   = (const float*)d_in[14];
    }
    float* out = (float*)d_out;

    const int TB = 256;
    const int GN4 = (NN / 4 + TB - 1) / TB;       // node kernels (float4)
    const int GE  = (EE + TB - 1) / TB;           // edge decode, 1/thread
    const int GS2 = (EE / 2 + TB - 1) / TB;       // scatter, 2/thread

    k_setup<<<GN4 + 2, TB>>>((const unsigned long long*)src,
                             W0, b0, W1, b1, W2, b2, W3, b3, W4, b4, W5, b5);
    k_edges<<<GE, TB>>>(src, dst);
    k_init<<<GN4, TB>>>(x);

    for (int k = 0; k < 5; k++) {
        k_scatter<<<GS2, TB>>>();
        k_post<<<GN4, TB>>>(k);
    }
    k_scatter<<<GS2, TB>>>();
    k_final<<<GN4, TB>>>(out);
}

// round 6
// speedup vs baseline: 1.0399x; 1.0120x over previous
#include <cuda_runtime.h>

#define NN 100000
#define EE 1600000
#define NPAD (98 * 1024)          // NN padded to scan granularity (98 blocks x 1024)

// Static device scratch (allocation-free per harness rules)
__device__ float g_rs[NN];        // ns[n] * r_k[n]  (gathered in scatter pass)
__device__ float g_acc[NN];       // edge-scatter accumulator
__device__ float g_ns[NN];        // out_deg^-1/2
__device__ float g_nd[NN];        // in_deg^-1/2
__device__ int2  g_edge[EE];      // decoded (src,dst) in input order
__device__ __align__(16) int2 g_sort[EE];  // (src,dst) sorted by src
__device__ int   g_cs[NPAD];      // src histogram (padded, zeroed)
__device__ int   g_cd[NPAD];      // dst histogram
__device__ int   g_cur[NPAD];     // running offsets for permute
__device__ int   g_part[98];      // per-block partial sums
__device__ int   g_base[98];      // exclusive block bases
__device__ float g_scal[8];       // s0..s5, w
__device__ int   g_is64;

// ---------------------------------------------------------------------------
// Fused setup: block 0 = collapse linear channel path to scalars; block 1 =
// index dtype probe (first 256 elems as u64: 2KB read, safe for either dtype;
// genuine int64 indices are all < NN, aliased int32 pairs exceed NN w.p. ~1);
// blocks 2.. = zero histograms + accumulator.
// ---------------------------------------------------------------------------
__global__ void k_setup(const unsigned long long* __restrict__ srcp,
                        const float* __restrict__ W0, const float* __restrict__ b0,
                        const float* __restrict__ W1, const float* __restrict__ b1,
                        const float* __restrict__ W2, const float* __restrict__ b2,
                        const float* __restrict__ W3, const float* __restrict__ b3,
                        const float* __restrict__ W4, const float* __restrict__ b4,
                        const float* __restrict__ W5, const float* __restrict__ b5) {
    int t = threadIdx.x;
    if (blockIdx.x == 0) {
        __shared__ float u5[32], u4[64], u3[128], u2[64], u1[32];
        if (t < 32) u5[t] = W5[t];
        __syncthreads();
        if (t < 64) { float s = 0.f; for (int j = 0; j < 32; j++) s += W4[t*32+j]*u5[j]; u4[t] = s; }
        __syncthreads();
        if (t < 128){ float s = 0.f; for (int j = 0; j < 64; j++) s += W3[t*64+j]*u4[j]; u3[t] = s; }
        __syncthreads();
        if (t < 64) { float s = 0.f; for (int j = 0; j < 128;j++) s += W2[t*128+j]*u3[j]; u2[t] = s; }
        __syncthreads();
        if (t < 32) { float s = 0.f; for (int j = 0; j < 64; j++) s += W1[t*64+j]*u2[j]; u1[t] = s; }
        __syncthreads();
        if (t == 0) {
            float w = 0.f, s0 = 0.f;
            for (int j = 0; j < 32; j++)  { w += W0[j]*u1[j]; s0 += b0[j]*u1[j]; }
            float s1 = 0.f; for (int j = 0; j < 64;  j++) s1 += b1[j]*u2[j];
            float s2 = 0.f; for (int j = 0; j < 128; j++) s2 += b2[j]*u3[j];
            float s3 = 0.f; for (int j = 0; j < 64;  j++) s3 += b3[j]*u4[j];
            float s4 = 0.f; for (int j = 0; j < 32;  j++) s4 += b4[j]*u5[j];
            g_scal[0]=s0; g_scal[1]=s1; g_scal[2]=s2; g_scal[3]=s3; g_scal[4]=s4;
            g_scal[5]=b5[0]; g_scal[6]=w;
        }
    } else if (blockIdx.x == 1) {
        int bad = (srcp[t] >= (unsigned long long)NN) ? 1 : 0;
        int any = __syncthreads_or(bad);
        if (t == 0) g_is64 = any ? 0 : 1;
    } else {
        int n = (blockIdx.x - 2) * blockDim.x + t;     // 0 .. NPAD/4-1
        if (n < NPAD / 4) {
            int4 zi = make_int4(0, 0, 0, 0);
            reinterpret_cast<int4*>(g_cs)[n] = zi;
            reinterpret_cast<int4*>(g_cd)[n] = zi;
            if (n < NN / 4)
                reinterpret_cast<float4*>(g_acc)[n] = make_float4(0.f, 0.f, 0.f, 0.f);
        }
    }
}

// Decode 1 edge/thread, clamp, store packed int2, build int histograms.
__global__ void k_edges(const void* __restrict__ srcv,
                        const void* __restrict__ dstv) {
    int e = blockIdx.x * blockDim.x + threadIdx.x;
    if (e < EE) {
        long long sl, dl;
        if (g_is64) {
            sl = ((const long long*)srcv)[e];
            dl = ((const long long*)dstv)[e];
        } else {
            sl = ((const int*)srcv)[e];
            dl = ((const int*)dstv)[e];
        }
        int s = (sl < 0) ? 0 : (sl >= NN ? NN - 1 : (int)sl);
        int d = (dl < 0) ? 0 : (dl >= NN ? NN - 1 : (int)dl);
        g_edge[e] = make_int2(s, d);
        atomicAdd(&g_cs[s], 1);
        atomicAdd(&g_cd[d], 1);
    }
}

// Scan stage 1: per-block (1024 elems) sums of g_cs.
__global__ void k_scan1() {
    int t = threadIdx.x, b = blockIdx.x;
    int4 c = reinterpret_cast<const int4*>(g_cs)[b * 256 + t];
    int v = c.x + c.y + c.z + c.w;
    __shared__ int sh[256];
    sh[t] = v; __syncthreads();
    for (int off = 128; off > 0; off >>= 1) {
        if (t < off) sh[t] += sh[t + off];
        __syncthreads();
    }
    if (t == 0) g_part[b] = sh[0];
}

// Scan stage 2: exclusive scan of the 98 block partials (single block).
__global__ void k_scan2() {
    int t = threadIdx.x;                       // 128 threads
    __shared__ int sh[128];
    int v = (t < 98) ? g_part[t] : 0;
    sh[t] = v; __syncthreads();
    for (int off = 1; off < 128; off <<= 1) {
        int a = (t >= off) ? sh[t - off] : 0;
        __syncthreads();
        sh[t] += a;
        __syncthreads();
    }
    if (t < 98) g_base[t] = sh[t] - v;         // exclusive
}

// Scan stage 3: per-element exclusive offsets -> g_cur.
__global__ void k_scan3() {
    int t = threadIdx.x, b = blockIdx.x;
    int4 c = reinterpret_cast<const int4*>(g_cs)[b * 256 + t];
    int tsum = c.x + c.y + c.z + c.w;
    __shared__ int sh[256];
    sh[t] = tsum; __syncthreads();
    for (int off = 1; off < 256; off <<= 1) {
        int a = (t >= off) ? sh[t - off] : 0;
        __syncthreads();
        sh[t] += a;
        __syncthreads();
    }
    int base = g_base[b] + sh[t] - tsum;       // exclusive across threads
    int4 o;
    o.x = base;
    o.y = o.x + c.x;
    o.z = o.y + c.y;
    o.w = o.z + c.z;
    reinterpret_cast<int4*>(g_cur)[b * 256 + t] = o;
}

// Permute edges into src-sorted order.
__global__ void k_perm() {
    int e = blockIdx.x * blockDim.x + threadIdx.x;
    if (e < EE) {
        int2 ed = g_edge[e];
        int p = atomicAdd(&g_cur[ed.x], 1);
        g_sort[p] = ed;
    }
}

// Finalize norms from int histograms; r0 = w*x; stage rs = ns*r0. (float4)
__global__ void k_init(const float* __restrict__ x) {
    int n = blockIdx.x * blockDim.x + threadIdx.x;
    if (n < NN / 4) {
        float w = g_scal[6];
        int4 cs = reinterpret_cast<const int4*>(g_cs)[n];
        int4 cd = reinterpret_cast<const int4*>(g_cd)[n];
        float4 xv = reinterpret_cast<const float4*>(x)[n];
        float4 ns, nd, rs;
        ns.x = rsqrtf(fmaxf((float)cs.x, 1.f)); nd.x = rsqrtf(fmaxf((float)cd.x, 1.f));
        ns.y = rsqrtf(fmaxf((float)cs.y, 1.f)); nd.y = rsqrtf(fmaxf((float)cd.y, 1.f));
        ns.z = rsqrtf(fmaxf((float)cs.z, 1.f)); nd.z = rsqrtf(fmaxf((float)cd.z, 1.f));
        ns.w = rsqrtf(fmaxf((float)cs.w, 1.f)); nd.w = rsqrtf(fmaxf((float)cd.w, 1.f));
        rs.x = ns.x * w * xv.x; rs.y = ns.y * w * xv.y;
        rs.z = ns.z * w * xv.z; rs.w = ns.w * w * xv.w;
        reinterpret_cast<float4*>(g_ns)[n] = ns;
        reinterpret_cast<float4*>(g_nd)[n] = nd;
        reinterpret_cast<float4*>(g_rs)[n] = rs;
    }
}

// One propagation hop over src-sorted edges: acc[dst] += rs[src].
// Gathers are now warp-coalesced (consecutive edges share src) -> few L1tex
// wavefronts; cost floor is the random REDs.
__global__ void k_scatter() {
    int i = blockIdx.x * blockDim.x + threadIdx.x;
    if (i < EE / 2) {
        int4 p = reinterpret_cast<const int4*>(g_sort)[i];   // (s0,d0,s1,d1)
        float v0 = __ldg(&g_rs[p.x]);
        float v1 = __ldg(&g_rs[p.z]);
        atomicAdd(&g_acc[p.y], v0);
        atomicAdd(&g_acc[p.w], v1);
    }
}

// r_{k+1} = nd*acc + s_k; stage rs = ns*r_{k+1}; re-zero acc. (float4)
__global__ void k_post(int k) {
    int n = blockIdx.x * blockDim.x + threadIdx.x;
    if (n < NN / 4) {
        float sk = g_scal[k];
        float4 nd = reinterpret_cast<float4*>(g_nd)[n];
        float4 ac = reinterpret_cast<float4*>(g_acc)[n];
        float4 ns = reinterpret_cast<float4*>(g_ns)[n];
        float4 rs;
        rs.x = ns.x * (nd.x * ac.x + sk);
        rs.y = ns.y * (nd.y * ac.y + sk);
        rs.z = ns.z * (nd.z * ac.z + sk);
        rs.w = ns.w * (nd.w * ac.w + sk);
        reinterpret_cast<float4*>(g_rs)[n] = rs;
        reinterpret_cast<float4*>(g_acc)[n] = make_float4(0.f, 0.f, 0.f, 0.f);
    }
}

// Final hop epilogue: out = |nd*acc + s5| (float4)
__global__ void k_final(float* __restrict__ out) {
    int n = blockIdx.x * blockDim.x + threadIdx.x;
    if (n < NN / 4) {
        float s5 = g_scal[5];
        float4 nd = reinterpret_cast<float4*>(g_nd)[n];
        float4 ac = reinterpret_cast<float4*>(g_acc)[n];
        float4 o;
        o.x = fabsf(nd.x * ac.x + s5);
        o.y = fabsf(nd.y * ac.y + s5);
        o.z = fabsf(nd.z * ac.z + s5);
        o.w = fabsf(nd.w * ac.w + s5);
        reinterpret_cast<float4*>(out)[n] = o;
    }
}

extern "C" void kernel_launch(void* const* d_in, const int* in_sizes, int n_in,
                              void* d_out, int out_size) {
    // Layout A (dict order): x, src, dst, W0,b0..W5,b5
    // Layout B (sorted):     W0..W5, b0..b5, dst, src, x
    const float *x, *W0, *b0, *W1, *b1, *W2, *b2, *W3, *b3, *W4, *b4, *W5, *b5;
    const void *src, *dst;

    if (in_sizes[0] == NN) {
        x   = (const float*)d_in[0];
        src = d_in[1];
        dst = d_in[2];
        W0 = (const float*)d_in[3];  b0 = (const float*)d_in[4];
        W1 = (const float*)d_in[5];  b1 = (const float*)d_in[6];
        W2 = (const float*)d_in[7];  b2 = (const float*)d_in[8];
        W3 = (const float*)d_in[9];  b3 = (const float*)d_in[10];
        W4 = (const float*)d_in[11]; b4 = (const float*)d_in[12];
        W5 = (const float*)d_in[13]; b5 = (const float*)d_in[14];
    } else {
        W0 = (const float*)d_in[0];  W1 = (const float*)d_in[1];
        W2 = (const float*)d_in[2];  W3 = (const float*)d_in[3];
        W4 = (const float*)d_in[4];  W5 = (const float*)d_in[5];
        b0 = (const float*)d_in[6];  b1 = (const float*)d_in[7];
        b2 = (const float*)d_in[8];  b3 = (const float*)d_in[9];
        b4 = (const float*)d_in[10]; b5 = (const float*)d_in[11];
        dst = d_in[12];
        src = d_in[13];
        x   = (const float*)d_in[14];
    }
    float* out = (float*)d_out;

    const int TB = 256;
    const int GZ  = NPAD / 4 / TB + 2;            // setup: 98 zero blocks + 2
    const int GN4 = (NN / 4 + TB - 1) / TB;       // 98
    const int GE  = (EE + TB - 1) / TB;           // 6250
    const int GS2 = (EE / 2 + TB - 1) / TB;       // 3125

    k_setup<<<GZ, TB>>>((const unsigned long long*)src,
                        W0, b0, W1, b1, W2, b2, W3, b3, W4, b4, W5, b5);
    k_edges<<<GE, TB>>>(src, dst);
    k_scan1<<<98, TB>>>();
    k_scan2<<<1, 128>>>();
    k_scan3<<<98, TB>>>();
    k_perm<<<GE, TB>>>();
    k_init<<<GN4, TB>>>(x);

    for (int k = 0; k < 5; k++) {
        k_scatter<<<GS2, TB>>>();
        k_post<<<GN4, TB>>>(k);
    }
    k_scatter<<<GS2, TB>>>();
    k_final<<<GN4, TB>>>(out);
}

// round 7
// speedup vs baseline: 1.2107x; 1.1642x over previous
#include <cuda_runtime.h>

#define NN 100000
#define EE 1600000
#define NPAD (98 * 1024)          // NN padded to scan granularity (98 blocks x 1024)

// Static device scratch (allocation-free per harness rules)
__device__ float g_rs[NN];        // ns[n] * r_k[n]  (gathered in scatter pass)
__device__ float g_acc[NN];       // edge-scatter accumulator
__device__ float g_ns[NN];        // out_deg^-1/2
__device__ float g_nd[NN];        // in_deg^-1/2
__device__ int2  g_edge[EE];      // decoded (src,dst) in input order
__device__ __align__(16) int2 g_sort[EE];  // (src,dst) sorted by dst
__device__ int   g_cs[NPAD];      // src histogram (out-degree)
__device__ int   g_cd[NPAD];      // dst histogram (in-degree, sort key)
__device__ int   g_cur[NPAD];     // running offsets for permute
__device__ int   g_part[98];      // per-block partial sums
__device__ int   g_base[98];      // exclusive block bases
__device__ int   g_tick;          // last-block ticket
__device__ float g_scal[8];       // s0..s5, w
__device__ int   g_is64;

// ---------------------------------------------------------------------------
// Fused setup: block 0 = collapse linear channel path to scalars; block 1 =
// index dtype probe (first 256 elems as u64: 2KB read, safe for either dtype;
// genuine int64 indices are all < NN, aliased int32 pairs exceed NN w.p. ~1);
// blocks 2.. = zero histograms + accumulator + ticket.
// ---------------------------------------------------------------------------
__global__ void k_setup(const unsigned long long* __restrict__ srcp,
                        const float* __restrict__ W0, const float* __restrict__ b0,
                        const float* __restrict__ W1, const float* __restrict__ b1,
                        const float* __restrict__ W2, const float* __restrict__ b2,
                        const float* __restrict__ W3, const float* __restrict__ b3,
                        const float* __restrict__ W4, const float* __restrict__ b4,
                        const float* __restrict__ W5, const float* __restrict__ b5) {
    int t = threadIdx.x;
    if (blockIdx.x == 0) {
        __shared__ float u5[32], u4[64], u3[128], u2[64], u1[32];
        if (t < 32) u5[t] = W5[t];
        __syncthreads();
        if (t < 64) { float s = 0.f; for (int j = 0; j < 32; j++) s += W4[t*32+j]*u5[j]; u4[t] = s; }
        __syncthreads();
        if (t < 128){ float s = 0.f; for (int j = 0; j < 64; j++) s += W3[t*64+j]*u4[j]; u3[t] = s; }
        __syncthreads();
        if (t < 64) { float s = 0.f; for (int j = 0; j < 128;j++) s += W2[t*128+j]*u3[j]; u2[t] = s; }
        __syncthreads();
        if (t < 32) { float s = 0.f; for (int j = 0; j < 64; j++) s += W1[t*64+j]*u2[j]; u1[t] = s; }
        __syncthreads();
        if (t == 0) {
            float w = 0.f, s0 = 0.f;
            for (int j = 0; j < 32; j++)  { w += W0[j]*u1[j]; s0 += b0[j]*u1[j]; }
            float s1 = 0.f; for (int j = 0; j < 64;  j++) s1 += b1[j]*u2[j];
            float s2 = 0.f; for (int j = 0; j < 128; j++) s2 += b2[j]*u3[j];
            float s3 = 0.f; for (int j = 0; j < 64;  j++) s3 += b3[j]*u4[j];
            float s4 = 0.f; for (int j = 0; j < 32;  j++) s4 += b4[j]*u5[j];
            g_scal[0]=s0; g_scal[1]=s1; g_scal[2]=s2; g_scal[3]=s3; g_scal[4]=s4;
            g_scal[5]=b5[0]; g_scal[6]=w;
            g_tick = 0;
        }
    } else if (blockIdx.x == 1) {
        int bad = (srcp[t] >= (unsigned long long)NN) ? 1 : 0;
        int any = __syncthreads_or(bad);
        if (t == 0) g_is64 = any ? 0 : 1;
    } else {
        int n = (blockIdx.x - 2) * blockDim.x + t;     // 0 .. NPAD/4-1
        if (n < NPAD / 4) {
            int4 zi = make_int4(0, 0, 0, 0);
            reinterpret_cast<int4*>(g_cs)[n] = zi;
            reinterpret_cast<int4*>(g_cd)[n] = zi;
            if (n < NN / 4)
                reinterpret_cast<float4*>(g_acc)[n] = make_float4(0.f, 0.f, 0.f, 0.f);
        }
    }
}

// Decode 1 edge/thread, clamp, store packed int2, build both histograms.
__global__ void k_edges(const void* __restrict__ srcv,
                        const void* __restrict__ dstv) {
    int e = blockIdx.x * blockDim.x + threadIdx.x;
    if (e < EE) {
        long long sl, dl;
        if (g_is64) {
            sl = ((const long long*)srcv)[e];
            dl = ((const long long*)dstv)[e];
        } else {
            sl = ((const int*)srcv)[e];
            dl = ((const int*)dstv)[e];
        }
        int s = (sl < 0) ? 0 : (sl >= NN ? NN - 1 : (int)sl);
        int d = (dl < 0) ? 0 : (dl >= NN ? NN - 1 : (int)dl);
        g_edge[e] = make_int2(s, d);
        atomicAdd(&g_cs[s], 1);
        atomicAdd(&g_cd[d], 1);
    }
}

// Fused scan stage 1+2: per-block sums of g_cd; the LAST block to finish
// exclusive-scans the 98 partials into g_base.
__global__ void k_scanA() {
    int t = threadIdx.x, b = blockIdx.x;
    int4 c = reinterpret_cast<const int4*>(g_cd)[b * 256 + t];
    int v = c.x + c.y + c.z + c.w;
    __shared__ int sh[256];
    sh[t] = v; __syncthreads();
    for (int off = 128; off > 0; off >>= 1) {
        if (t < off) sh[t] += sh[t + off];
        __syncthreads();
    }
    __shared__ int is_last;
    if (t == 0) {
        g_part[b] = sh[0];
        __threadfence();
        is_last = (atomicAdd(&g_tick, 1) == gridDim.x - 1);
    }
    __syncthreads();
    if (is_last) {
        // 98-element exclusive scan, done by one block (first 128 threads)
        __shared__ int sp[128];
        int pv = (t < 98) ? g_part[t] : 0;
        if (t < 128) sp[t] = pv;
        __syncthreads();
        for (int off = 1; off < 128; off <<= 1) {
            int a = (t < 128 && t >= off) ? sp[t - off] : 0;
            __syncthreads();
            if (t < 128) sp[t] += a;
            __syncthreads();
        }
        if (t < 98) g_base[t] = sp[t] - pv;    // exclusive
    }
}

// Scan stage 3: per-element exclusive offsets of g_cd -> g_cur.
__global__ void k_scan3() {
    int t = threadIdx.x, b = blockIdx.x;
    int4 c = reinterpret_cast<const int4*>(g_cd)[b * 256 + t];
    int tsum = c.x + c.y + c.z + c.w;
    __shared__ int sh[256];
    sh[t] = tsum; __syncthreads();
    for (int off = 1; off < 256; off <<= 1) {
        int a = (t >= off) ? sh[t - off] : 0;
        __syncthreads();
        sh[t] += a;
        __syncthreads();
    }
    int base = g_base[b] + sh[t] - tsum;       // exclusive across threads
    int4 o;
    o.x = base;
    o.y = o.x + c.x;
    o.z = o.y + c.y;
    o.w = o.z + c.z;
    reinterpret_cast<int4*>(g_cur)[b * 256 + t] = o;
}

// Permute edges into dst-sorted order.
__global__ void k_perm() {
    int e = blockIdx.x * blockDim.x + threadIdx.x;
    if (e < EE) {
        int2 ed = g_edge[e];
        int p = atomicAdd(&g_cur[ed.y], 1);
        g_sort[p] = ed;
    }
}

// Finalize norms from int histograms; r0 = w*x; stage rs = ns*r0. (float4)
__global__ void k_init(const float* __restrict__ x) {
    int n = blockIdx.x * blockDim.x + threadIdx.x;
    if (n < NN / 4) {
        float w = g_scal[6];
        int4 cs = reinterpret_cast<const int4*>(g_cs)[n];
        int4 cd = reinterpret_cast<const int4*>(g_cd)[n];
        float4 xv = reinterpret_cast<const float4*>(x)[n];
        float4 ns, nd, rs;
        ns.x = rsqrtf(fmaxf((float)cs.x, 1.f)); nd.x = rsqrtf(fmaxf((float)cd.x, 1.f));
        ns.y = rsqrtf(fmaxf((float)cs.y, 1.f)); nd.y = rsqrtf(fmaxf((float)cd.y, 1.f));
        ns.z = rsqrtf(fmaxf((float)cs.z, 1.f)); nd.z = rsqrtf(fmaxf((float)cd.z, 1.f));
        ns.w = rsqrtf(fmaxf((float)cs.w, 1.f)); nd.w = rsqrtf(fmaxf((float)cd.w, 1.f));
        rs.x = ns.x * w * xv.x; rs.y = ns.y * w * xv.y;
        rs.z = ns.z * w * xv.z; rs.w = ns.w * w * xv.w;
        reinterpret_cast<float4*>(g_ns)[n] = ns;
        reinterpret_cast<float4*>(g_nd)[n] = nd;
        reinterpret_cast<float4*>(g_rs)[n] = rs;
    }
}

// One propagation hop over dst-sorted edges with warp-segmented reduction:
// contiguous equal-dst runs are summed inside the warp via shfl; only run
// tails issue atomicAdd (~E/deg + boundary atomics ≈ 100K instead of 1.6M).
__global__ void k_scatter() {
    int e = blockIdx.x * blockDim.x + threadIdx.x;
    if (e >= EE) return;
    int2 ed = g_sort[e];
    float v = __ldg(&g_rs[ed.x]);
    int d = ed.y;
    unsigned lane = threadIdx.x & 31;

    int dprev = __shfl_up_sync(0xFFFFFFFFu, d, 1);
    bool head = (lane == 0) || (d != dprev);
    unsigned hm = __ballot_sync(0xFFFFFFFFu, head);
    // Highest head position <= my lane (lane 0 is always head -> nonzero).
    unsigned below = hm & ((2u << lane) - 1u);
    int start = 31 - __clz(below);

#pragma unroll
    for (int off = 1; off < 32; off <<= 1) {
        float u = __shfl_up_sync(0xFFFFFFFFu, v, off);
        if ((int)lane - off >= start) v += u;
    }
    // Tail lane of each run writes the run sum.
    bool tail = (lane == 31) || ((hm >> (lane + 1)) & 1u);
    if (tail) atomicAdd(&g_acc[d], v);
}

// r_{k+1} = nd*acc + s_k; stage rs = ns*r_{k+1}; re-zero acc. (float4)
__global__ void k_post(int k) {
    int n = blockIdx.x * blockDim.x + threadIdx.x;
    if (n < NN / 4) {
        float sk = g_scal[k];
        float4 nd = reinterpret_cast<float4*>(g_nd)[n];
        float4 ac = reinterpret_cast<float4*>(g_acc)[n];
        float4 ns = reinterpret_cast<float4*>(g_ns)[n];
        float4 rs;
        rs.x = ns.x * (nd.x * ac.x + sk);
        rs.y = ns.y * (nd.y * ac.y + sk);
        rs.z = ns.z * (nd.z * ac.z + sk);
        rs.w = ns.w * (nd.w * ac.w + sk);
        reinterpret_cast<float4*>(g_rs)[n] = rs;
        reinterpret_cast<float4*>(g_acc)[n] = make_float4(0.f, 0.f, 0.f, 0.f);
    }
}

// Final hop epilogue: out = |nd*acc + s5| (float4)
__global__ void k_final(float* __restrict__ out) {
    int n = blockIdx.x * blockDim.x + threadIdx.x;
    if (n < NN / 4) {
        float s5 = g_scal[5];
        float4 nd = reinterpret_cast<float4*>(g_nd)[n];
        float4 ac = reinterpret_cast<float4*>(g_acc)[n];
        float4 o;
        o.x = fabsf(nd.x * ac.x + s5);
        o.y = fabsf(nd.y * ac.y + s5);
        o.z = fabsf(nd.z * ac.z + s5);
        o.w = fabsf(nd.w * ac.w + s5);
        reinterpret_cast<float4*>(out)[n] = o;
    }
}

extern "C" void kernel_launch(void* const* d_in, const int* in_sizes, int n_in,
                              void* d_out, int out_size) {
    // Layout A (dict order): x, src, dst, W0,b0..W5,b5
    // Layout B (sorted):     W0..W5, b0..b5, dst, src, x
    const float *x, *W0, *b0, *W1, *b1, *W2, *b2, *W3, *b3, *W4, *b4, *W5, *b5;
    const void *src, *dst;

    if (in_sizes[0] == NN) {
        x   = (const float*)d_in[0];
        src = d_in[1];
        dst = d_in[2];
        W0 = (const float*)d_in[3];  b0 = (const float*)d_in[4];
        W1 = (const float*)d_in[5];  b1 = (const float*)d_in[6];
        W2 = (const float*)d_in[7];  b2 = (const float*)d_in[8];
        W3 = (const float*)d_in[9];  b3 = (const float*)d_in[10];
        W4 = (const float*)d_in[11]; b4 = (const float*)d_in[12];
        W5 = (const float*)d_in[13]; b5 = (const float*)d_in[14];
    } else {
        W0 = (const float*)d_in[0];  W1 = (const float*)d_in[1];
        W2 = (const float*)d_in[2];  W3 = (const float*)d_in[3];
        W4 = (const float*)d_in[4];  W5 = (const float*)d_in[5];
        b0 = (const float*)d_in[6];  b1 = (const float*)d_in[7];
        b2 = (const float*)d_in[8];  b3 = (const float*)d_in[9];
        b4 = (const float*)d_in[10]; b5 = (const float*)d_in[11];
        dst = d_in[12];
        src = d_in[13];
        x   = (const float*)d_in[14];
    }
    float* out = (float*)d_out;

    const int TB = 256;
    const int GZ  = NPAD / 4 / TB + 2;            // setup: 98 zero blocks + 2
    const int GN4 = (NN / 4 + TB - 1) / TB;       // 98
    const int GE  = (EE + TB - 1) / TB;           // 6250

    k_setup<<<GZ, TB>>>((const unsigned long long*)src,
                        W0, b0, W1, b1, W2, b2, W3, b3, W4, b4, W5, b5);
    k_edges<<<GE, TB>>>(src, dst);
    k_scanA<<<98, TB>>>();
    k_scan3<<<98, TB>>>();
    k_perm<<<GE, TB>>>();
    k_init<<<GN4, TB>>>(x);

    for (int k = 0; k < 5; k++) {
        k_scatter<<<GE, TB>>>();
        k_post<<<GN4, TB>>>(k);
    }
    k_scatter<<<GE, TB>>>();
    k_final<<<GN4, TB>>>(out);
}